// round 10
// baseline (speedup 1.0000x reference)
#include <cuda_runtime.h>
#include <cuda_bf16.h>
#include <math.h>
#include <stdint.h>

// Problem: B=4, S=4096, D=1024  (single-head attention, fp32 I/O)
#define BATCH 4
#define SEQ   4096
#define DIM   1024
#define MTOT  (BATCH*SEQ)   // 16384

// ---------------------------------------------------------------------------
// Static device scratch (~600 MB total)
// ---------------------------------------------------------------------------
__device__ __align__(256) __nv_bfloat16 g_xh[(size_t)MTOT * DIM];
__device__ __align__(256) __nv_bfloat16 g_xl[(size_t)MTOT * DIM];
__device__ __align__(256) __nv_bfloat16 g_Wh[3][(size_t)DIM * DIM];
__device__ __align__(256) __nv_bfloat16 g_Wl[3][(size_t)DIM * DIM];
__device__ __align__(256) __nv_bfloat16 g_Qh[(size_t)MTOT * DIM];
__device__ __align__(256) __nv_bfloat16 g_Ql[(size_t)MTOT * DIM];
__device__ __align__(256) __nv_bfloat16 g_Kh[(size_t)MTOT * DIM];
__device__ __align__(256) __nv_bfloat16 g_Kl[(size_t)MTOT * DIM];
__device__ __align__(256) float         g_V [(size_t)MTOT * DIM];
__device__ __align__(256) __nv_bfloat16 g_Vth[(size_t)BATCH * DIM * SEQ];
__device__ __align__(256) __nv_bfloat16 g_Vtl[(size_t)BATCH * DIM * SEQ];
// Union buffer: fp32 scores, then overwritten in-place by split-bf16 P.
// Row r: fp32 Sc row = 16KB; after softmax the same row holds Ph (8KB) + Pl (8KB).
__device__ __align__(256) float         g_SP[(size_t)BATCH * SEQ * SEQ];

// ---------------------------------------------------------------------------
// PTX helpers — baseline (non arch-variant) instructions only
// ---------------------------------------------------------------------------
__device__ __forceinline__ uint32_t smem_u32(const void* p) {
    uint32_t a;
    asm("{ .reg .u64 t; cvta.to.shared.u64 t, %1; cvt.u32.u64 %0, t; }"
        : "=r"(a) : "l"(p));
    return a;
}
__device__ __forceinline__ uint32_t swz128(uint32_t o) { return o ^ ((o >> 3) & 0x70); }

__device__ __forceinline__ void cp16(uint32_t dst, const void* src) {
    asm volatile("cp.async.cg.shared.global [%0], [%1], 16;"
                 :: "r"(dst), "l"(__cvta_generic_to_global(src)) : "memory");
}
#define CP_COMMIT() asm volatile("cp.async.commit_group;" ::: "memory")
#define CP_WAIT1()  asm volatile("cp.async.wait_group 1;" ::: "memory")

__device__ __forceinline__ void ldsm_x4(uint32_t& r0, uint32_t& r1, uint32_t& r2,
                                        uint32_t& r3, uint32_t addr) {
    asm volatile("ldmatrix.sync.aligned.m8n8.x4.shared.b16 {%0,%1,%2,%3}, [%4];"
                 : "=r"(r0), "=r"(r1), "=r"(r2), "=r"(r3) : "r"(addr));
}
__device__ __forceinline__ void mma_bf16(float* d, const uint32_t* a, const uint32_t* b) {
    asm volatile(
        "mma.sync.aligned.m16n8k16.row.col.f32.bf16.bf16.f32 "
        "{%0,%1,%2,%3}, {%4,%5,%6,%7}, {%8,%9}, {%0,%1,%2,%3};"
        : "+f"(d[0]), "+f"(d[1]), "+f"(d[2]), "+f"(d[3])
        : "r"(a[0]), "r"(a[1]), "r"(a[2]), "r"(a[3]), "r"(b[0]), "r"(b[1]));
}

// ---------------------------------------------------------------------------
// Split-bf16 tensor-core GEMM:  C[M,N] = alpha * (A_hi+A_lo) @ (B_hi+B_lo)^T
//   CTA tile 256x128, K chunk 64, 2-stage cp.async pipeline.
//   8 warps in 4(m) x 2(n); warp tile 64x64 (4 m-frags x 8 n-frags).
//   3 MMAs per k-step (hh + hl + lh), fp32 register accumulators.
//   EPI 0: fp32 out (alpha);  EPI 1: split hi/lo bf16 out.
// ---------------------------------------------------------------------------
#define KCHUNK       64
#define A_TILE_B     32768              // 256 rows * 128B
#define B_TILE_B     16384              // 128 rows * 128B
#define STAGE_BYTES  (2*A_TILE_B + 2*B_TILE_B)   // 98304
#define OFF_AHI      0
#define OFF_ALO      A_TILE_B
#define OFF_BHI      (2*A_TILE_B)
#define OFF_BLO      (2*A_TILE_B + B_TILE_B)
#define NSTAGES      2
#define GEMM_SMEM    (NSTAGES * STAGE_BYTES)     // 196608 B

template <int EPI>
__global__ void __launch_bounds__(256, 1)
gemm_mma(const __nv_bfloat16* __restrict__ Ah, const __nv_bfloat16* __restrict__ Al,
         const __nv_bfloat16* __restrict__ Bh, const __nv_bfloat16* __restrict__ Bl,
         float* __restrict__ Cf, __nv_bfloat16* __restrict__ Ch, __nv_bfloat16* __restrict__ Cl,
         int K, int lda, int ldb, int ldc, float alpha,
         long long sA, long long sB, long long sC)
{
    extern __shared__ __align__(1024) char smem[];
    const uint32_t sbase = smem_u32(smem);
    const int tid  = threadIdx.x;
    const int wid  = tid >> 5, lane = tid & 31;
    const int wm   = wid & 3;          // 0..3  (m: 64-row slice)
    const int wn   = wid >> 2;         // 0..1  (n: 64-col slice)

    Ah += blockIdx.z * sA;  Al += blockIdx.z * sA;
    Bh += blockIdx.z * sB;  Bl += blockIdx.z * sB;
    const int m0 = blockIdx.y * 256;
    const int n0 = blockIdx.x * 128;

    // ---- tile loader: 6144 x 16B cp.async per chunk (24 per thread) ----
    auto load_chunk = [&](int c) {
        const uint32_t stage = sbase + (c & (NSTAGES - 1)) * STAGE_BYTES;
        const int kb = c * KCHUNK;
        #pragma unroll
        for (int i = 0; i < 24; i++) {
            const int idx = tid + i * 256;
            const __nv_bfloat16* gp;
            uint32_t dst;
            if (i < 8) {                      // Ahi: idx 0..2047
                const int r = idx >> 3, seg = idx & 7;
                gp  = Ah + (long long)(m0 + r) * lda + kb + seg * 8;
                dst = stage + OFF_AHI + swz128(r * 128 + seg * 16);
            } else if (i < 16) {              // Alo
                const int w = idx - 2048, r = w >> 3, seg = w & 7;
                gp  = Al + (long long)(m0 + r) * lda + kb + seg * 8;
                dst = stage + OFF_ALO + swz128(r * 128 + seg * 16);
            } else if (i < 20) {              // Bhi: 1024 slots
                const int w = idx - 4096, r = w >> 3, seg = w & 7;
                gp  = Bh + (long long)(n0 + r) * ldb + kb + seg * 8;
                dst = stage + OFF_BHI + swz128(r * 128 + seg * 16);
            } else {                          // Blo
                const int w = idx - 5120, r = w >> 3, seg = w & 7;
                gp  = Bl + (long long)(n0 + r) * ldb + kb + seg * 8;
                dst = stage + OFF_BLO + swz128(r * 128 + seg * 16);
            }
            cp16(dst, gp);
        }
        CP_COMMIT();
    };

    load_chunk(0);
    load_chunk(1);

    float acc[4][8][4];
    #pragma unroll
    for (int i = 0; i < 4; i++)
        #pragma unroll
        for (int j = 0; j < 8; j++)
            #pragma unroll
            for (int q = 0; q < 4; q++) acc[i][j][q] = 0.f;

    const int lrow = lane & 15;          // row within 16-row group
    const int lkof = (lane >> 4) * 16;   // 16B chunk select (k halves)

    const int C = K / KCHUNK;
    for (int c = 0; c < C; c++) {
        CP_WAIT1();                      // chunk c resident
        __syncthreads();
        const uint32_t st = sbase + (c & (NSTAGES - 1)) * STAGE_BYTES;

        #pragma unroll
        for (int k16 = 0; k16 < 4; k16++) {
            const uint32_t kb = k16 * 32 + lkof;
            uint32_t ah[4][4], al[4][4];
            #pragma unroll
            for (int mf = 0; mf < 4; mf++) {
                const uint32_t ro = swz128((wm * 64 + mf * 16 + lrow) * 128 + kb);
                ldsm_x4(ah[mf][0], ah[mf][1], ah[mf][2], ah[mf][3], st + OFF_AHI + ro);
                ldsm_x4(al[mf][0], al[mf][1], al[mf][2], al[mf][3], st + OFF_ALO + ro);
            }
            #pragma unroll
            for (int p = 0; p < 4; p++) {   // B pair p covers n-frags 2p, 2p+1
                const uint32_t ro = swz128((wn * 64 + p * 16 + lrow) * 128 + kb);
                uint32_t bh[2][2], bl[2][2];
                uint32_t r0, r1, r2, r3;
                ldsm_x4(r0, r1, r2, r3, st + OFF_BHI + ro);
                bh[0][0] = r0; bh[0][1] = r2; bh[1][0] = r1; bh[1][1] = r3;
                ldsm_x4(r0, r1, r2, r3, st + OFF_BLO + ro);
                bl[0][0] = r0; bl[0][1] = r2; bl[1][0] = r1; bl[1][1] = r3;
                #pragma unroll
                for (int mf = 0; mf < 4; mf++)
                    #pragma unroll
                    for (int h = 0; h < 2; h++) {
                        float* a4 = acc[mf][2*p + h];
                        mma_bf16(a4, ah[mf], bh[h]);
                        mma_bf16(a4, ah[mf], bl[h]);
                        mma_bf16(a4, al[mf], bh[h]);
                    }
            }
        }
        __syncthreads();                 // all warps done reading stage c
        if (c + NSTAGES < C) load_chunk(c + NSTAGES);
        else CP_COMMIT();                // keep per-thread group count uniform
    }

    // ---- epilogue ----
    const int tq = lane >> 2;       // 0..7 (row within 8)
    const int tr = (lane & 3) * 2;  // col pair
    if (EPI == 0) {
        float* Cb = Cf + blockIdx.z * sC;
        #pragma unroll
        for (int mf = 0; mf < 4; mf++) {
            const int r = m0 + wm * 64 + mf * 16 + tq;
            #pragma unroll
            for (int nf = 0; nf < 8; nf++) {
                const int col = n0 + wn * 64 + nf * 8 + tr;
                float2 v0 = { acc[mf][nf][0] * alpha, acc[mf][nf][1] * alpha };
                float2 v1 = { acc[mf][nf][2] * alpha, acc[mf][nf][3] * alpha };
                *(float2*)&Cb[(long long)r * ldc + col]       = v0;
                *(float2*)&Cb[(long long)(r + 8) * ldc + col] = v1;
            }
        }
    } else {
        #pragma unroll
        for (int mf = 0; mf < 4; mf++) {
            const int r = m0 + wm * 64 + mf * 16 + tq;
            #pragma unroll
            for (int nf = 0; nf < 8; nf++) {
                const int col = n0 + wn * 64 + nf * 8 + tr;
                #pragma unroll
                for (int h = 0; h < 2; h++) {
                    const long long o = (long long)(r + 8 * h) * ldc + col;
                    float v0 = acc[mf][nf][2*h], v1 = acc[mf][nf][2*h+1];
                    __nv_bfloat16 h0 = __float2bfloat16(v0);
                    __nv_bfloat16 h1 = __float2bfloat16(v1);
                    __nv_bfloat16 l0 = __float2bfloat16(v0 - __bfloat162float(h0));
                    __nv_bfloat16 l1 = __float2bfloat16(v1 - __bfloat162float(h1));
                    __nv_bfloat162 hh = __halves2bfloat162(h0, h1);
                    __nv_bfloat162 ll = __halves2bfloat162(l0, l1);
                    *(uint32_t*)&Ch[o] = *(uint32_t*)&hh;
                    *(uint32_t*)&Cl[o] = *(uint32_t*)&ll;
                }
            }
        }
    }
}

// ---------------------------------------------------------------------------
// fp32 -> split bf16 (hi/lo)
// ---------------------------------------------------------------------------
__global__ void __launch_bounds__(256)
split_f32(const float* __restrict__ in, __nv_bfloat16* __restrict__ hi,
          __nv_bfloat16* __restrict__ lo, long long n4)
{
    long long i = (long long)blockIdx.x * blockDim.x + threadIdx.x;
    if (i >= n4) return;
    float4 v = ((const float4*)in)[i];
    __nv_bfloat16 h0 = __float2bfloat16(v.x), h1 = __float2bfloat16(v.y);
    __nv_bfloat16 h2 = __float2bfloat16(v.z), h3 = __float2bfloat16(v.w);
    __nv_bfloat162 a = __halves2bfloat162(h0, h1), b = __halves2bfloat162(h2, h3);
    uint2 uh = { *(uint32_t*)&a, *(uint32_t*)&b };
    __nv_bfloat16 l0 = __float2bfloat16(v.x - __bfloat162float(h0));
    __nv_bfloat16 l1 = __float2bfloat16(v.y - __bfloat162float(h1));
    __nv_bfloat16 l2 = __float2bfloat16(v.z - __bfloat162float(h2));
    __nv_bfloat16 l3 = __float2bfloat16(v.w - __bfloat162float(h3));
    __nv_bfloat162 c = __halves2bfloat162(l0, l1), d = __halves2bfloat162(l2, l3);
    uint2 ulv = { *(uint32_t*)&c, *(uint32_t*)&d };
    ((uint2*)hi)[i] = uh;
    ((uint2*)lo)[i] = ulv;
}

// ---------------------------------------------------------------------------
// V [b][s][d] fp32 -> Vt hi/lo [b][d][s] split bf16 (32x32 smem transpose)
// ---------------------------------------------------------------------------
__global__ void __launch_bounds__(256)
transpose_split(const float* __restrict__ V, __nv_bfloat16* __restrict__ Th,
                __nv_bfloat16* __restrict__ Tl)
{
    __shared__ float t[32][33];
    const int b = blockIdx.z;
    const int s0 = blockIdx.x * 32, d0 = blockIdx.y * 32;
    const int tx = threadIdx.x & 31, ty = threadIdx.x >> 5;  // 32x8
    const float* Vb = V + (long long)b * SEQ * DIM;
    #pragma unroll
    for (int j = 0; j < 4; j++)
        t[ty + 8*j][tx] = Vb[(long long)(s0 + ty + 8*j) * DIM + d0 + tx];
    __syncthreads();
    __nv_bfloat16* Thb = Th + (long long)b * DIM * SEQ;
    __nv_bfloat16* Tlb = Tl + (long long)b * DIM * SEQ;
    #pragma unroll
    for (int j = 0; j < 4; j++) {
        float v = t[tx][ty + 8*j];
        __nv_bfloat16 h = __float2bfloat16(v);
        __nv_bfloat16 l = __float2bfloat16(v - __bfloat162float(h));
        long long o = (long long)(d0 + ty + 8*j) * SEQ + s0 + tx;
        Thb[o] = h;  Tlb[o] = l;
    }
}

// ---------------------------------------------------------------------------
// Row softmax (4096 cols), IN-PLACE: reads fp32 row, writes split-bf16 P
// into the same 16KB row (Ph first 8KB, Pl second 8KB). One block per row.
// ---------------------------------------------------------------------------
__device__ __forceinline__ float warpMax(float v) {
    #pragma unroll
    for (int o = 16; o; o >>= 1) v = fmaxf(v, __shfl_xor_sync(0xffffffffu, v, o));
    return v;
}
__device__ __forceinline__ float warpSum(float v) {
    #pragma unroll
    for (int o = 16; o; o >>= 1) v += __shfl_xor_sync(0xffffffffu, v, o);
    return v;
}

__global__ void __launch_bounds__(256)
softmax_inplace(float* __restrict__ SP)
{
    __shared__ float shm[8], shs[8];
    const size_t row = blockIdx.x;
    float* rowp = SP + row * (size_t)SEQ;
    const float4* r4 = (const float4*)rowp;
    const int tid = threadIdx.x, lane = tid & 31, wid = tid >> 5;

    float4 v[4];
    float m = -3.4e38f;
    #pragma unroll
    for (int i = 0; i < 4; i++) {
        v[i] = r4[tid + i * 256];
        m = fmaxf(m, fmaxf(fmaxf(v[i].x, v[i].y), fmaxf(v[i].z, v[i].w)));
    }
    m = warpMax(m);
    if (lane == 0) shm[wid] = m;
    __syncthreads();
    float bm = shm[0];
    #pragma unroll
    for (int i = 1; i < 8; i++) bm = fmaxf(bm, shm[i]);

    float s = 0.f;
    #pragma unroll
    for (int i = 0; i < 4; i++) {
        v[i].x = __expf(v[i].x - bm); v[i].y = __expf(v[i].y - bm);
        v[i].z = __expf(v[i].z - bm); v[i].w = __expf(v[i].w - bm);
        s += v[i].x + v[i].y + v[i].z + v[i].w;
    }
    s = warpSum(s);
    if (lane == 0) shs[wid] = s;
    __syncthreads();
    float bs = 0.f;
    #pragma unroll
    for (int i = 0; i < 8; i++) bs += shs[i];
    const float inv = 1.0f / bs;

    uint2* ph = (uint2*)rowp;
    uint2* pl = (uint2*)((__nv_bfloat16*)rowp + SEQ);
    #pragma unroll
    for (int i = 0; i < 4; i++) {
        float x0 = v[i].x * inv, x1 = v[i].y * inv, x2 = v[i].z * inv, x3 = v[i].w * inv;
        __nv_bfloat16 h0 = __float2bfloat16(x0), h1 = __float2bfloat16(x1);
        __nv_bfloat16 h2 = __float2bfloat16(x2), h3 = __float2bfloat16(x3);
        __nv_bfloat162 a = __halves2bfloat162(h0, h1), b = __halves2bfloat162(h2, h3);
        ph[tid + i * 256] = uint2{ *(uint32_t*)&a, *(uint32_t*)&b };
        __nv_bfloat16 l0 = __float2bfloat16(x0 - __bfloat162float(h0));
        __nv_bfloat16 l1 = __float2bfloat16(x1 - __bfloat162float(h1));
        __nv_bfloat16 l2 = __float2bfloat16(x2 - __bfloat162float(h2));
        __nv_bfloat16 l3 = __float2bfloat16(x3 - __bfloat162float(h3));
        __nv_bfloat162 c = __halves2bfloat162(l0, l1), d = __halves2bfloat162(l2, l3);
        pl[tid + i * 256] = uint2{ *(uint32_t*)&c, *(uint32_t*)&d };
    }
}

// ---------------------------------------------------------------------------
// Launch
// ---------------------------------------------------------------------------
extern "C" void kernel_launch(void* const* d_in, const int* in_sizes, int n_in,
                              void* d_out, int out_size)
{
    const float* x  = (const float*)d_in[0];
    const float* Wq = (const float*)d_in[1];
    const float* Wk = (const float*)d_in[2];
    const float* Wv = (const float*)d_in[3];
    float* out = (float*)d_out;

    __nv_bfloat16 *xh, *xl, *Wh, *Wl, *Qh, *Ql, *Kh, *Kl, *Vth, *Vtl;
    float *V, *SP;
    cudaGetSymbolAddress((void**)&xh, g_xh);   cudaGetSymbolAddress((void**)&xl, g_xl);
    cudaGetSymbolAddress((void**)&Wh, g_Wh);   cudaGetSymbolAddress((void**)&Wl, g_Wl);
    cudaGetSymbolAddress((void**)&Qh, g_Qh);   cudaGetSymbolAddress((void**)&Ql, g_Ql);
    cudaGetSymbolAddress((void**)&Kh, g_Kh);   cudaGetSymbolAddress((void**)&Kl, g_Kl);
    cudaGetSymbolAddress((void**)&V,  g_V);
    cudaGetSymbolAddress((void**)&Vth, g_Vth); cudaGetSymbolAddress((void**)&Vtl, g_Vtl);
    cudaGetSymbolAddress((void**)&SP, g_SP);

    cudaFuncSetAttribute(gemm_mma<0>, cudaFuncAttributeMaxDynamicSharedMemorySize, GEMM_SMEM);
    cudaFuncSetAttribute(gemm_mma<1>, cudaFuncAttributeMaxDynamicSharedMemorySize, GEMM_SMEM);

    const float scale = 1.0f / 32.0f;  // D^-0.5

    // 1) split inputs to hi/lo bf16
    split_f32<<<(MTOT * (long long)DIM / 4 + 255) / 256, 256>>>(x, xh, xl, (long long)MTOT * DIM / 4);
    const long long wn4 = (long long)DIM * DIM / 4;
    split_f32<<<(wn4 + 255) / 256, 256>>>(Wq, Wh + 0 * (size_t)DIM * DIM, Wl + 0 * (size_t)DIM * DIM, wn4);
    split_f32<<<(wn4 + 255) / 256, 256>>>(Wk, Wh + 1 * (size_t)DIM * DIM, Wl + 1 * (size_t)DIM * DIM, wn4);
    split_f32<<<(wn4 + 255) / 256, 256>>>(Wv, Wh + 2 * (size_t)DIM * DIM, Wl + 2 * (size_t)DIM * DIM, wn4);

    // 2) projections: [16384,1024] = x @ W^T   (M tiles of 256)
    {
        dim3 grid(DIM / 128, MTOT / 256, 1);
        gemm_mma<1><<<grid, 256, GEMM_SMEM>>>(xh, xl, Wh + 0 * (size_t)DIM * DIM, Wl + 0 * (size_t)DIM * DIM,
                                              nullptr, Qh, Ql, DIM, DIM, DIM, DIM, 1.f, 0, 0, 0);
        gemm_mma<1><<<grid, 256, GEMM_SMEM>>>(xh, xl, Wh + 1 * (size_t)DIM * DIM, Wl + 1 * (size_t)DIM * DIM,
                                              nullptr, Kh, Kl, DIM, DIM, DIM, DIM, 1.f, 0, 0, 0);
        gemm_mma<0><<<grid, 256, GEMM_SMEM>>>(xh, xl, Wh + 2 * (size_t)DIM * DIM, Wl + 2 * (size_t)DIM * DIM,
                                              V, nullptr, nullptr, DIM, DIM, DIM, DIM, 1.f, 0, 0, 0);
    }

    // 3) V -> Vt split (bf16 [b][d][s])
    transpose_split<<<dim3(SEQ / 32, DIM / 32, BATCH), 256>>>(V, Vth, Vtl);

    // 4) scores: SP[b] = scale * Q[b] @ K[b]^T   (fp32)
    gemm_mma<0><<<dim3(SEQ / 128, SEQ / 256, BATCH), 256, GEMM_SMEM>>>(
        Qh, Ql, Kh, Kl, SP, nullptr, nullptr,
        DIM, DIM, DIM, SEQ, scale,
        (long long)SEQ * DIM, (long long)SEQ * DIM, (long long)SEQ * SEQ);

    // 5) softmax in-place -> split bf16 P (row stride 2*SEQ bf16)
    softmax_inplace<<<BATCH * SEQ, 256>>>(SP);

    // 6) out[b] = P[b] @ Vt[b]^T   (Ph rows at stride 2*SEQ, Pl = Ph + SEQ)
    {
        const __nv_bfloat16* Phb = (const __nv_bfloat16*)SP;
        const __nv_bfloat16* Plb = Phb + SEQ;
        gemm_mma<0><<<dim3(DIM / 128, SEQ / 256, BATCH), 256, GEMM_SMEM>>>(
            Phb, Plb, Vth, Vtl, out, nullptr, nullptr,
            SEQ, 2 * SEQ, SEQ, DIM, 1.f,
            (long long)SEQ * 2 * SEQ, (long long)DIM * SEQ, (long long)SEQ * DIM);
    }
}

// round 11
// speedup vs baseline: 1.0129x; 1.0129x over previous
#include <cuda_runtime.h>
#include <cuda_bf16.h>
#include <math.h>
#include <stdint.h>

// Problem: B=4, S=4096, D=1024  (single-head attention, fp32 I/O)
#define BATCH 4
#define SEQ   4096
#define DIM   1024
#define MTOT  (BATCH*SEQ)   // 16384

// ---------------------------------------------------------------------------
// Static device scratch (~600 MB total)
// ---------------------------------------------------------------------------
__device__ __align__(256) __nv_bfloat16 g_xh[(size_t)MTOT * DIM];
__device__ __align__(256) __nv_bfloat16 g_xl[(size_t)MTOT * DIM];
__device__ __align__(256) __nv_bfloat16 g_Wh[3][(size_t)DIM * DIM];
__device__ __align__(256) __nv_bfloat16 g_Wl[3][(size_t)DIM * DIM];
__device__ __align__(256) __nv_bfloat16 g_Qh[(size_t)MTOT * DIM];
__device__ __align__(256) __nv_bfloat16 g_Ql[(size_t)MTOT * DIM];
__device__ __align__(256) __nv_bfloat16 g_Kh[(size_t)MTOT * DIM];
__device__ __align__(256) __nv_bfloat16 g_Kl[(size_t)MTOT * DIM];
__device__ __align__(256) float         g_V [(size_t)MTOT * DIM];
__device__ __align__(256) __nv_bfloat16 g_Vth[(size_t)BATCH * DIM * SEQ];
__device__ __align__(256) __nv_bfloat16 g_Vtl[(size_t)BATCH * DIM * SEQ];
// Union buffer: fp32 scores, then overwritten in-place by split-bf16 P.
// Row r: fp32 Sc row = 16KB; after softmax the same row holds Ph (8KB) + Pl (8KB).
__device__ __align__(256) float         g_SP[(size_t)BATCH * SEQ * SEQ];

// ---------------------------------------------------------------------------
// PTX helpers — baseline (non arch-variant) instructions only
// ---------------------------------------------------------------------------
__device__ __forceinline__ uint32_t smem_u32(const void* p) {
    uint32_t a;
    asm("{ .reg .u64 t; cvta.to.shared.u64 t, %1; cvt.u32.u64 %0, t; }"
        : "=r"(a) : "l"(p));
    return a;
}
__device__ __forceinline__ uint32_t swz128(uint32_t o) { return o ^ ((o >> 3) & 0x70); }

__device__ __forceinline__ void cp16(uint32_t dst, const void* src) {
    asm volatile("cp.async.cg.shared.global [%0], [%1], 16;"
                 :: "r"(dst), "l"(__cvta_generic_to_global(src)) : "memory");
}
#define CP_COMMIT() asm volatile("cp.async.commit_group;" ::: "memory")
#define CP_WAIT1()  asm volatile("cp.async.wait_group 1;" ::: "memory")

__device__ __forceinline__ void ldsm_x4(uint32_t& r0, uint32_t& r1, uint32_t& r2,
                                        uint32_t& r3, uint32_t addr) {
    asm volatile("ldmatrix.sync.aligned.m8n8.x4.shared.b16 {%0,%1,%2,%3}, [%4];"
                 : "=r"(r0), "=r"(r1), "=r"(r2), "=r"(r3) : "r"(addr));
}
__device__ __forceinline__ void mma_bf16(float* d, const uint32_t* a, const uint32_t* b) {
    asm volatile(
        "mma.sync.aligned.m16n8k16.row.col.f32.bf16.bf16.f32 "
        "{%0,%1,%2,%3}, {%4,%5,%6,%7}, {%8,%9}, {%0,%1,%2,%3};"
        : "+f"(d[0]), "+f"(d[1]), "+f"(d[2]), "+f"(d[3])
        : "r"(a[0]), "r"(a[1]), "r"(a[2]), "r"(a[3]), "r"(b[0]), "r"(b[1]));
}

// ---------------------------------------------------------------------------
// Split-bf16 tensor-core GEMM:  C[M,N] = alpha * (A_hi+A_lo) @ (B_hi+B_lo)^T
//   CTA tile 128x128, K chunk 64, THREE-stage cp.async pipeline with eager
//   load issue: per chunk ->  wait / sync / issue loads(c+2) / compute(c).
//   Slot (c+2)%3 was last read in iteration c-1, whose readers all passed
//   the top-of-loop barrier of iteration c => overwrite is race-free with
//   a SINGLE barrier per chunk.
//   8 warps, 2(m) x 4(n); warp tile 64x32 (4 m-frags x 4 n-frags).
//   3 MMAs per k-step (hh + hl + lh), fp32 register accumulators.
//   EPI 0: fp32 out (alpha);  EPI 1: split hi/lo bf16 out.
// ---------------------------------------------------------------------------
#define KCHUNK       64
#define TILE_BYTES   16384              // 128 rows * 128B
#define STAGE_BYTES  (4 * TILE_BYTES)   // Ahi, Alo, Bhi, Blo
#define NSTAGES      3
#define GEMM_SMEM    (NSTAGES * STAGE_BYTES)   // 196608 B

template <int EPI>
__global__ void __launch_bounds__(256, 1)
gemm_mma(const __nv_bfloat16* __restrict__ Ah, const __nv_bfloat16* __restrict__ Al,
         const __nv_bfloat16* __restrict__ Bh, const __nv_bfloat16* __restrict__ Bl,
         float* __restrict__ Cf, __nv_bfloat16* __restrict__ Ch, __nv_bfloat16* __restrict__ Cl,
         int K, int lda, int ldb, int ldc, float alpha,
         long long sA, long long sB, long long sC)
{
    extern __shared__ __align__(1024) char smem[];
    const uint32_t sbase = smem_u32(smem);
    const int tid  = threadIdx.x;
    const int wid  = tid >> 5, lane = tid & 31;
    const int wm   = wid & 1;          // 0..1  (m: 64-row slice)
    const int wn   = wid >> 1;         // 0..3  (n: 32-col slice)

    Ah += blockIdx.z * sA;  Al += blockIdx.z * sA;
    Bh += blockIdx.z * sB;  Bl += blockIdx.z * sB;
    const int m0 = blockIdx.y * 128;
    const int n0 = blockIdx.x * 128;

    // ---- tile loader: 4096 x 16B cp.async per chunk (16 per thread) ----
    auto load_chunk = [&](int c) {
        const uint32_t stage = sbase + (c % NSTAGES) * STAGE_BYTES;
        const int kb = c * KCHUNK;
        #pragma unroll
        for (int i = 0; i < 16; i++) {
            const int idx = tid + i * 256;
            const int t   = i >> 2;           // 0:Ahi 1:Alo 2:Bhi 3:Blo
            const int w   = idx & 1023;
            const int r   = w >> 3;           // row 0..127
            const int seg = w & 7;            // 16B segment
            const __nv_bfloat16* gp;
            if (t == 0)      gp = Ah + (long long)(m0 + r) * lda + kb + seg * 8;
            else if (t == 1) gp = Al + (long long)(m0 + r) * lda + kb + seg * 8;
            else if (t == 2) gp = Bh + (long long)(n0 + r) * ldb + kb + seg * 8;
            else             gp = Bl + (long long)(n0 + r) * ldb + kb + seg * 8;
            cp16(stage + t * TILE_BYTES + swz128(r * 128 + seg * 16), gp);
        }
        CP_COMMIT();
    };

    load_chunk(0);
    load_chunk(1);

    float acc[4][4][4];
    #pragma unroll
    for (int i = 0; i < 4; i++)
        #pragma unroll
        for (int j = 0; j < 4; j++)
            #pragma unroll
            for (int q = 0; q < 4; q++) acc[i][j][q] = 0.f;

    // per-lane ldmatrix row/chunk components
    const int lrow = lane & 15;          // row within 16-row group
    const int lkof = (lane >> 4) * 16;   // 16B chunk select (k halves)
    const int arow = wm * 64 + lrow;     // A row base for this lane
    const int brow = wn * 32 + lrow;     // B row base for this lane

    const int C = K / KCHUNK;
    for (int c = 0; c < C; c++) {
        CP_WAIT1();                      // chunk c resident (1 newest pending)
        __syncthreads();                 // all warps past iter c-1 compute

        // eager: issue loads for chunk c+2 into slot (c+2)%3 (safe: its last
        // readers finished in iter c-1, before the barrier above)
        if (c + 2 < C) load_chunk(c + 2);
        else CP_COMMIT();                // keep per-thread group count uniform

        const uint32_t st = sbase + (c % NSTAGES) * STAGE_BYTES;

        #pragma unroll
        for (int k16 = 0; k16 < 4; k16++) {
            const uint32_t kb = k16 * 32 + lkof;
            uint32_t ah[4][4], al[4][4], bh[4][2], bl[4][2];
            #pragma unroll
            for (int mf = 0; mf < 4; mf++) {
                const uint32_t ro = swz128((arow + mf * 16) * 128 + kb);
                ldsm_x4(ah[mf][0], ah[mf][1], ah[mf][2], ah[mf][3], st + ro);
                ldsm_x4(al[mf][0], al[mf][1], al[mf][2], al[mf][3], st + TILE_BYTES + ro);
            }
            #pragma unroll
            for (int p = 0; p < 2; p++) {   // covers n-frags 2p, 2p+1
                const uint32_t ro = swz128((brow + p * 16) * 128 + kb);
                uint32_t r0, r1, r2, r3;
                ldsm_x4(r0, r1, r2, r3, st + 2 * TILE_BYTES + ro);
                bh[2*p][0] = r0; bh[2*p][1] = r2; bh[2*p+1][0] = r1; bh[2*p+1][1] = r3;
                ldsm_x4(r0, r1, r2, r3, st + 3 * TILE_BYTES + ro);
                bl[2*p][0] = r0; bl[2*p][1] = r2; bl[2*p+1][0] = r1; bl[2*p+1][1] = r3;
            }
            #pragma unroll
            for (int mf = 0; mf < 4; mf++)
                #pragma unroll
                for (int nf = 0; nf < 4; nf++) {
                    mma_bf16(acc[mf][nf], ah[mf], bh[nf]);
                    mma_bf16(acc[mf][nf], ah[mf], bl[nf]);
                    mma_bf16(acc[mf][nf], al[mf], bh[nf]);
                }
        }
        // no trailing barrier: next iteration's top barrier protects slots
    }

    // ---- epilogue ----
    const int tq = lane >> 2;       // 0..7 (row within 8)
    const int tr = (lane & 3) * 2;  // col pair
    if (EPI == 0) {
        float* Cb = Cf + blockIdx.z * sC;
        #pragma unroll
        for (int mf = 0; mf < 4; mf++) {
            const int r = m0 + wm * 64 + mf * 16 + tq;
            #pragma unroll
            for (int nf = 0; nf < 4; nf++) {
                const int col = n0 + wn * 32 + nf * 8 + tr;
                float2 v0 = { acc[mf][nf][0] * alpha, acc[mf][nf][1] * alpha };
                float2 v1 = { acc[mf][nf][2] * alpha, acc[mf][nf][3] * alpha };
                *(float2*)&Cb[(long long)r * ldc + col]       = v0;
                *(float2*)&Cb[(long long)(r + 8) * ldc + col] = v1;
            }
        }
    } else {
        #pragma unroll
        for (int mf = 0; mf < 4; mf++) {
            const int r = m0 + wm * 64 + mf * 16 + tq;
            #pragma unroll
            for (int nf = 0; nf < 4; nf++) {
                const int col = n0 + wn * 32 + nf * 8 + tr;
                #pragma unroll
                for (int h = 0; h < 2; h++) {
                    const long long o = (long long)(r + 8 * h) * ldc + col;
                    float v0 = acc[mf][nf][2*h], v1 = acc[mf][nf][2*h+1];
                    __nv_bfloat16 h0 = __float2bfloat16(v0);
                    __nv_bfloat16 h1 = __float2bfloat16(v1);
                    __nv_bfloat16 l0 = __float2bfloat16(v0 - __bfloat162float(h0));
                    __nv_bfloat16 l1 = __float2bfloat16(v1 - __bfloat162float(h1));
                    __nv_bfloat162 hh = __halves2bfloat162(h0, h1);
                    __nv_bfloat162 ll = __halves2bfloat162(l0, l1);
                    *(uint32_t*)&Ch[o] = *(uint32_t*)&hh;
                    *(uint32_t*)&Cl[o] = *(uint32_t*)&ll;
                }
            }
        }
    }
}

// ---------------------------------------------------------------------------
// fp32 -> split bf16 (hi/lo)
// ---------------------------------------------------------------------------
__global__ void __launch_bounds__(256)
split_f32(const float* __restrict__ in, __nv_bfloat16* __restrict__ hi,
          __nv_bfloat16* __restrict__ lo, long long n4)
{
    long long i = (long long)blockIdx.x * blockDim.x + threadIdx.x;
    if (i >= n4) return;
    float4 v = ((const float4*)in)[i];
    __nv_bfloat16 h0 = __float2bfloat16(v.x), h1 = __float2bfloat16(v.y);
    __nv_bfloat16 h2 = __float2bfloat16(v.z), h3 = __float2bfloat16(v.w);
    __nv_bfloat162 a = __halves2bfloat162(h0, h1), b = __halves2bfloat162(h2, h3);
    uint2 uh = { *(uint32_t*)&a, *(uint32_t*)&b };
    __nv_bfloat16 l0 = __float2bfloat16(v.x - __bfloat162float(h0));
    __nv_bfloat16 l1 = __float2bfloat16(v.y - __bfloat162float(h1));
    __nv_bfloat16 l2 = __float2bfloat16(v.z - __bfloat162float(h2));
    __nv_bfloat16 l3 = __float2bfloat16(v.w - __bfloat162float(h3));
    __nv_bfloat162 c = __halves2bfloat162(l0, l1), d = __halves2bfloat162(l2, l3);
    uint2 ulv = { *(uint32_t*)&c, *(uint32_t*)&d };
    ((uint2*)hi)[i] = uh;
    ((uint2*)lo)[i] = ulv;
}

// ---------------------------------------------------------------------------
// V [b][s][d] fp32 -> Vt hi/lo [b][d][s] split bf16 (32x32 smem transpose)
// ---------------------------------------------------------------------------
__global__ void __launch_bounds__(256)
transpose_split(const float* __restrict__ V, __nv_bfloat16* __restrict__ Th,
                __nv_bfloat16* __restrict__ Tl)
{
    __shared__ float t[32][33];
    const int b = blockIdx.z;
    const int s0 = blockIdx.x * 32, d0 = blockIdx.y * 32;
    const int tx = threadIdx.x & 31, ty = threadIdx.x >> 5;  // 32x8
    const float* Vb = V + (long long)b * SEQ * DIM;
    #pragma unroll
    for (int j = 0; j < 4; j++)
        t[ty + 8*j][tx] = Vb[(long long)(s0 + ty + 8*j) * DIM + d0 + tx];
    __syncthreads();
    __nv_bfloat16* Thb = Th + (long long)b * DIM * SEQ;
    __nv_bfloat16* Tlb = Tl + (long long)b * DIM * SEQ;
    #pragma unroll
    for (int j = 0; j < 4; j++) {
        float v = t[tx][ty + 8*j];
        __nv_bfloat16 h = __float2bfloat16(v);
        __nv_bfloat16 l = __float2bfloat16(v - __bfloat162float(h));
        long long o = (long long)(d0 + ty + 8*j) * SEQ + s0 + tx;
        Thb[o] = h;  Tlb[o] = l;
    }
}

// ---------------------------------------------------------------------------
// Row softmax (4096 cols), IN-PLACE: reads fp32 row, writes split-bf16 P
// into the same 16KB row (Ph first 8KB, Pl second 8KB). One block per row.
// ---------------------------------------------------------------------------
__device__ __forceinline__ float warpMax(float v) {
    #pragma unroll
    for (int o = 16; o; o >>= 1) v = fmaxf(v, __shfl_xor_sync(0xffffffffu, v, o));
    return v;
}
__device__ __forceinline__ float warpSum(float v) {
    #pragma unroll
    for (int o = 16; o; o >>= 1) v += __shfl_xor_sync(0xffffffffu, v, o);
    return v;
}

__global__ void __launch_bounds__(256)
softmax_inplace(float* __restrict__ SP)
{
    __shared__ float shm[8], shs[8];
    const size_t row = blockIdx.x;
    float* rowp = SP + row * (size_t)SEQ;
    const float4* r4 = (const float4*)rowp;
    const int tid = threadIdx.x, lane = tid & 31, wid = tid >> 5;

    float4 v[4];
    float m = -3.4e38f;
    #pragma unroll
    for (int i = 0; i < 4; i++) {
        v[i] = r4[tid + i * 256];
        m = fmaxf(m, fmaxf(fmaxf(v[i].x, v[i].y), fmaxf(v[i].z, v[i].w)));
    }
    m = warpMax(m);
    if (lane == 0) shm[wid] = m;
    __syncthreads();
    float bm = shm[0];
    #pragma unroll
    for (int i = 1; i < 8; i++) bm = fmaxf(bm, shm[i]);

    float s = 0.f;
    #pragma unroll
    for (int i = 0; i < 4; i++) {
        v[i].x = __expf(v[i].x - bm); v[i].y = __expf(v[i].y - bm);
        v[i].z = __expf(v[i].z - bm); v[i].w = __expf(v[i].w - bm);
        s += v[i].x + v[i].y + v[i].z + v[i].w;
    }
    s = warpSum(s);
    if (lane == 0) shs[wid] = s;
    __syncthreads();
    float bs = 0.f;
    #pragma unroll
    for (int i = 0; i < 8; i++) bs += shs[i];
    const float inv = 1.0f / bs;

    uint2* ph = (uint2*)rowp;
    uint2* pl = (uint2*)((__nv_bfloat16*)rowp + SEQ);
    #pragma unroll
    for (int i = 0; i < 4; i++) {
        float x0 = v[i].x * inv, x1 = v[i].y * inv, x2 = v[i].z * inv, x3 = v[i].w * inv;
        __nv_bfloat16 h0 = __float2bfloat16(x0), h1 = __float2bfloat16(x1);
        __nv_bfloat16 h2 = __float2bfloat16(x2), h3 = __float2bfloat16(x3);
        __nv_bfloat162 a = __halves2bfloat162(h0, h1), b = __halves2bfloat162(h2, h3);
        ph[tid + i * 256] = uint2{ *(uint32_t*)&a, *(uint32_t*)&b };
        __nv_bfloat16 l0 = __float2bfloat16(x0 - __bfloat162float(h0));
        __nv_bfloat16 l1 = __float2bfloat16(x1 - __bfloat162float(h1));
        __nv_bfloat16 l2 = __float2bfloat16(x2 - __bfloat162float(h2));
        __nv_bfloat16 l3 = __float2bfloat16(x3 - __bfloat162float(h3));
        __nv_bfloat162 c = __halves2bfloat162(l0, l1), d = __halves2bfloat162(l2, l3);
        pl[tid + i * 256] = uint2{ *(uint32_t*)&c, *(uint32_t*)&d };
    }
}

// ---------------------------------------------------------------------------
// Launch
// ---------------------------------------------------------------------------
extern "C" void kernel_launch(void* const* d_in, const int* in_sizes, int n_in,
                              void* d_out, int out_size)
{
    const float* x  = (const float*)d_in[0];
    const float* Wq = (const float*)d_in[1];
    const float* Wk = (const float*)d_in[2];
    const float* Wv = (const float*)d_in[3];
    float* out = (float*)d_out;

    __nv_bfloat16 *xh, *xl, *Wh, *Wl, *Qh, *Ql, *Kh, *Kl, *Vth, *Vtl;
    float *V, *SP;
    cudaGetSymbolAddress((void**)&xh, g_xh);   cudaGetSymbolAddress((void**)&xl, g_xl);
    cudaGetSymbolAddress((void**)&Wh, g_Wh);   cudaGetSymbolAddress((void**)&Wl, g_Wl);
    cudaGetSymbolAddress((void**)&Qh, g_Qh);   cudaGetSymbolAddress((void**)&Ql, g_Ql);
    cudaGetSymbolAddress((void**)&Kh, g_Kh);   cudaGetSymbolAddress((void**)&Kl, g_Kl);
    cudaGetSymbolAddress((void**)&V,  g_V);
    cudaGetSymbolAddress((void**)&Vth, g_Vth); cudaGetSymbolAddress((void**)&Vtl, g_Vtl);
    cudaGetSymbolAddress((void**)&SP, g_SP);

    cudaFuncSetAttribute(gemm_mma<0>, cudaFuncAttributeMaxDynamicSharedMemorySize, GEMM_SMEM);
    cudaFuncSetAttribute(gemm_mma<1>, cudaFuncAttributeMaxDynamicSharedMemorySize, GEMM_SMEM);

    const float scale = 1.0f / 32.0f;  // D^-0.5

    // 1) split inputs to hi/lo bf16
    split_f32<<<(MTOT * (long long)DIM / 4 + 255) / 256, 256>>>(x, xh, xl, (long long)MTOT * DIM / 4);
    const long long wn4 = (long long)DIM * DIM / 4;
    split_f32<<<(wn4 + 255) / 256, 256>>>(Wq, Wh + 0 * (size_t)DIM * DIM, Wl + 0 * (size_t)DIM * DIM, wn4);
    split_f32<<<(wn4 + 255) / 256, 256>>>(Wk, Wh + 1 * (size_t)DIM * DIM, Wl + 1 * (size_t)DIM * DIM, wn4);
    split_f32<<<(wn4 + 255) / 256, 256>>>(Wv, Wh + 2 * (size_t)DIM * DIM, Wl + 2 * (size_t)DIM * DIM, wn4);

    // 2) projections: [16384,1024] = x @ W^T
    {
        dim3 grid(DIM / 128, MTOT / 128, 1);
        gemm_mma<1><<<grid, 256, GEMM_SMEM>>>(xh, xl, Wh + 0 * (size_t)DIM * DIM, Wl + 0 * (size_t)DIM * DIM,
                                              nullptr, Qh, Ql, DIM, DIM, DIM, DIM, 1.f, 0, 0, 0);
        gemm_mma<1><<<grid, 256, GEMM_SMEM>>>(xh, xl, Wh + 1 * (size_t)DIM * DIM, Wl + 1 * (size_t)DIM * DIM,
                                              nullptr, Kh, Kl, DIM, DIM, DIM, DIM, 1.f, 0, 0, 0);
        gemm_mma<0><<<grid, 256, GEMM_SMEM>>>(xh, xl, Wh + 2 * (size_t)DIM * DIM, Wl + 2 * (size_t)DIM * DIM,
                                              V, nullptr, nullptr, DIM, DIM, DIM, DIM, 1.f, 0, 0, 0);
    }

    // 3) V -> Vt split (bf16 [b][d][s])
    transpose_split<<<dim3(SEQ / 32, DIM / 32, BATCH), 256>>>(V, Vth, Vtl);

    // 4) scores: SP[b] = scale * Q[b] @ K[b]^T   (fp32)
    gemm_mma<0><<<dim3(SEQ / 128, SEQ / 128, BATCH), 256, GEMM_SMEM>>>(
        Qh, Ql, Kh, Kl, SP, nullptr, nullptr,
        DIM, DIM, DIM, SEQ, scale,
        (long long)SEQ * DIM, (long long)SEQ * DIM, (long long)SEQ * SEQ);

    // 5) softmax in-place -> split bf16 P (row stride 2*SEQ bf16)
    softmax_inplace<<<BATCH * SEQ, 256>>>(SP);

    // 6) out[b] = P[b] @ Vt[b]^T   (Ph rows at stride 2*SEQ, Pl = Ph + SEQ)
    {
        const __nv_bfloat16* Phb = (const __nv_bfloat16*)SP;
        const __nv_bfloat16* Plb = Phb + SEQ;
        gemm_mma<0><<<dim3(DIM / 128, SEQ / 128, BATCH), 256, GEMM_SMEM>>>(
            Phb, Plb, Vth, Vtl, out, nullptr, nullptr,
            SEQ, 2 * SEQ, SEQ, DIM, 1.f,
            (long long)SEQ * 2 * SEQ, (long long)DIM * SEQ, (long long)SEQ * DIM);
    }
}

// round 12
// speedup vs baseline: 1.0496x; 1.0363x over previous
#include <cuda_runtime.h>
#include <cuda_bf16.h>
#include <math.h>
#include <stdint.h>

// Problem: B=4, S=4096, D=1024  (single-head attention, fp32 I/O)
#define BATCH 4
#define SEQ   4096
#define DIM   1024
#define MTOT  (BATCH*SEQ)   // 16384

// ---------------------------------------------------------------------------
// Static device scratch (~600 MB total)
// ---------------------------------------------------------------------------
__device__ __align__(256) __nv_bfloat16 g_xh[(size_t)MTOT * DIM];
__device__ __align__(256) __nv_bfloat16 g_xl[(size_t)MTOT * DIM];
__device__ __align__(256) __nv_bfloat16 g_Wh[3][(size_t)DIM * DIM];
__device__ __align__(256) __nv_bfloat16 g_Wl[3][(size_t)DIM * DIM];
__device__ __align__(256) __nv_bfloat16 g_Qh[(size_t)MTOT * DIM];
__device__ __align__(256) __nv_bfloat16 g_Ql[(size_t)MTOT * DIM];
__device__ __align__(256) __nv_bfloat16 g_Kh[(size_t)MTOT * DIM];
__device__ __align__(256) __nv_bfloat16 g_Kl[(size_t)MTOT * DIM];
__device__ __align__(256) float         g_V [(size_t)MTOT * DIM];
__device__ __align__(256) __nv_bfloat16 g_Vth[(size_t)BATCH * DIM * SEQ];
__device__ __align__(256) __nv_bfloat16 g_Vtl[(size_t)BATCH * DIM * SEQ];
// Union buffer: fp32 scores, then overwritten in-place by split-bf16 P.
// Row r: fp32 Sc row = 16KB; after softmax the same row holds Ph (8KB) + Pl (8KB).
__device__ __align__(256) float         g_SP[(size_t)BATCH * SEQ * SEQ];

// ---------------------------------------------------------------------------
// PTX helpers — baseline (non arch-variant) instructions only
// ---------------------------------------------------------------------------
__device__ __forceinline__ uint32_t smem_u32(const void* p) {
    uint32_t a;
    asm("{ .reg .u64 t; cvta.to.shared.u64 t, %1; cvt.u32.u64 %0, t; }"
        : "=r"(a) : "l"(p));
    return a;
}
// SW64 swizzle for 64-byte rows (8 rows x 64B atom)
__device__ __forceinline__ uint32_t swz64(uint32_t o) { return o ^ ((o >> 3) & 0x30); }

__device__ __forceinline__ void cp16(uint32_t dst, const void* src) {
    asm volatile("cp.async.cg.shared.global [%0], [%1], 16;"
                 :: "r"(dst), "l"(__cvta_generic_to_global(src)) : "memory");
}
#define CP_COMMIT() asm volatile("cp.async.commit_group;" ::: "memory")
#define CP_WAIT2()  asm volatile("cp.async.wait_group 2;" ::: "memory")

__device__ __forceinline__ void ldsm_x4(uint32_t& r0, uint32_t& r1, uint32_t& r2,
                                        uint32_t& r3, uint32_t addr) {
    asm volatile("ldmatrix.sync.aligned.m8n8.x4.shared.b16 {%0,%1,%2,%3}, [%4];"
                 : "=r"(r0), "=r"(r1), "=r"(r2), "=r"(r3) : "r"(addr));
}
__device__ __forceinline__ void mma_bf16(float* d, const uint32_t* a, const uint32_t* b) {
    asm volatile(
        "mma.sync.aligned.m16n8k16.row.col.f32.bf16.bf16.f32 "
        "{%0,%1,%2,%3}, {%4,%5,%6,%7}, {%8,%9}, {%0,%1,%2,%3};"
        : "+f"(d[0]), "+f"(d[1]), "+f"(d[2]), "+f"(d[3])
        : "r"(a[0]), "r"(a[1]), "r"(a[2]), "r"(a[3]), "r"(b[0]), "r"(b[1]));
}

// ---------------------------------------------------------------------------
// Split-bf16 tensor-core GEMM:  C[M,N] = alpha * (A_hi+A_lo) @ (B_hi+B_lo)^T
//   CTA tile 128x128, K chunk 32 (64B SW64 rows), 3-stage cp.async pipeline,
//   96KB smem -> TWO CTAs PER SM for cross-CTA latency hiding.
//   8 warps, 2(m) x 4(n); warp tile 64x32 (4 m-frags x 4 n-frags).
//   3 MMAs per k-step (hh + hl + lh), fp32 register accumulators.
//   Accumulation order per element identical to the 3151us baseline.
//   EPI 0: fp32 out (alpha);  EPI 1: split hi/lo bf16 out.
// ---------------------------------------------------------------------------
#define KCHUNK       32
#define TILE_BYTES   8192               // 128 rows * 64B
#define STAGE_BYTES  (4 * TILE_BYTES)   // Ahi, Alo, Bhi, Blo = 32KB
#define NSTAGES      3
#define GEMM_SMEM    (NSTAGES * STAGE_BYTES)   // 98304 B -> 2 CTAs/SM

template <int EPI>
__global__ void __launch_bounds__(256, 2)
gemm_mma(const __nv_bfloat16* __restrict__ Ah, const __nv_bfloat16* __restrict__ Al,
         const __nv_bfloat16* __restrict__ Bh, const __nv_bfloat16* __restrict__ Bl,
         float* __restrict__ Cf, __nv_bfloat16* __restrict__ Ch, __nv_bfloat16* __restrict__ Cl,
         int K, int lda, int ldb, int ldc, float alpha,
         long long sA, long long sB, long long sC)
{
    extern __shared__ __align__(1024) char smem[];
    const uint32_t sbase = smem_u32(smem);
    const int tid  = threadIdx.x;
    const int wid  = tid >> 5, lane = tid & 31;
    const int wm   = wid & 1;          // 0..1  (m: 64-row slice)
    const int wn   = wid >> 1;         // 0..3  (n: 32-col slice)

    Ah += blockIdx.z * sA;  Al += blockIdx.z * sA;
    Bh += blockIdx.z * sB;  Bl += blockIdx.z * sB;
    const int m0 = blockIdx.y * 128;
    const int n0 = blockIdx.x * 128;

    // ---- tile loader: 2048 x 16B cp.async per chunk (8 per thread) ----
    // tile = 128 rows x 64B (4 x 16B segs); SW64 swizzle
    auto load_chunk = [&](int c) {
        const uint32_t stage = sbase + (c % NSTAGES) * STAGE_BYTES;
        const int kb = c * KCHUNK;
        #pragma unroll
        for (int i = 0; i < 8; i++) {
            const int idx = tid + i * 256;
            const int t   = idx >> 9;         // 0:Ahi 1:Alo 2:Bhi 3:Blo
            const int w   = idx & 511;
            const int r   = w >> 2;           // row 0..127
            const int seg = w & 3;            // 16B segment (0..3)
            const __nv_bfloat16* gp;
            if (t == 0)      gp = Ah + (long long)(m0 + r) * lda + kb + seg * 8;
            else if (t == 1) gp = Al + (long long)(m0 + r) * lda + kb + seg * 8;
            else if (t == 2) gp = Bh + (long long)(n0 + r) * ldb + kb + seg * 8;
            else             gp = Bl + (long long)(n0 + r) * ldb + kb + seg * 8;
            cp16(stage + t * TILE_BYTES + swz64(r * 64 + seg * 16), gp);
        }
        CP_COMMIT();
    };

    load_chunk(0);
    load_chunk(1);
    load_chunk(2);

    float acc[4][4][4];
    #pragma unroll
    for (int i = 0; i < 4; i++)
        #pragma unroll
        for (int j = 0; j < 4; j++)
            #pragma unroll
            for (int q = 0; q < 4; q++) acc[i][j][q] = 0.f;

    // per-lane ldmatrix row/chunk components (same lane->fragment mapping
    // as the passing baseline; only row stride + swizzle changed)
    const int lrow = lane & 15;          // row within 16-row group
    const int lkof = (lane >> 4) * 16;   // 16B chunk select (k halves)
    const int arow = wm * 64 + lrow;     // A row base for this lane
    const int brow = wn * 32 + lrow;     // B row base for this lane

    const int C = K / KCHUNK;
    for (int c = 0; c < C; c++) {
        CP_WAIT2();                      // <=2 pending -> chunk c resident
        __syncthreads();
        const uint32_t st = sbase + (c % NSTAGES) * STAGE_BYTES;

        #pragma unroll
        for (int k16 = 0; k16 < 2; k16++) {
            const uint32_t kb = k16 * 32 + lkof;
            // B fragments first (16 live regs), A transient per mf
            uint32_t bh[4][2], bl[4][2];
            #pragma unroll
            for (int p = 0; p < 2; p++) {   // covers n-frags 2p, 2p+1
                const uint32_t ro = swz64((brow + p * 16) * 64 + kb);
                uint32_t r0, r1, r2, r3;
                ldsm_x4(r0, r1, r2, r3, st + 2 * TILE_BYTES + ro);
                bh[2*p][0] = r0; bh[2*p][1] = r2; bh[2*p+1][0] = r1; bh[2*p+1][1] = r3;
                ldsm_x4(r0, r1, r2, r3, st + 3 * TILE_BYTES + ro);
                bl[2*p][0] = r0; bl[2*p][1] = r2; bl[2*p+1][0] = r1; bl[2*p+1][1] = r3;
            }
            #pragma unroll
            for (int mf = 0; mf < 4; mf++) {
                uint32_t ah[4], al[4];
                const uint32_t ro = swz64((arow + mf * 16) * 64 + kb);
                ldsm_x4(ah[0], ah[1], ah[2], ah[3], st + ro);
                ldsm_x4(al[0], al[1], al[2], al[3], st + TILE_BYTES + ro);
                #pragma unroll
                for (int nf = 0; nf < 4; nf++) {
                    mma_bf16(acc[mf][nf], ah, bh[nf]);
                    mma_bf16(acc[mf][nf], ah, bl[nf]);
                    mma_bf16(acc[mf][nf], al, bh[nf]);
                }
            }
        }
        __syncthreads();                 // all warps done reading stage c
        if (c + NSTAGES < C) load_chunk(c + NSTAGES);
        else CP_COMMIT();                // keep per-thread group count uniform
    }

    // ---- epilogue ----
    const int tq = lane >> 2;       // 0..7 (row within 8)
    const int tr = (lane & 3) * 2;  // col pair
    if (EPI == 0) {
        float* Cb = Cf + blockIdx.z * sC;
        #pragma unroll
        for (int mf = 0; mf < 4; mf++) {
            const int r = m0 + wm * 64 + mf * 16 + tq;
            #pragma unroll
            for (int nf = 0; nf < 4; nf++) {
                const int col = n0 + wn * 32 + nf * 8 + tr;
                float2 v0 = { acc[mf][nf][0] * alpha, acc[mf][nf][1] * alpha };
                float2 v1 = { acc[mf][nf][2] * alpha, acc[mf][nf][3] * alpha };
                *(float2*)&Cb[(long long)r * ldc + col]       = v0;
                *(float2*)&Cb[(long long)(r + 8) * ldc + col] = v1;
            }
        }
    } else {
        #pragma unroll
        for (int mf = 0; mf < 4; mf++) {
            const int r = m0 + wm * 64 + mf * 16 + tq;
            #pragma unroll
            for (int nf = 0; nf < 4; nf++) {
                const int col = n0 + wn * 32 + nf * 8 + tr;
                #pragma unroll
                for (int h = 0; h < 2; h++) {
                    const long long o = (long long)(r + 8 * h) * ldc + col;
                    float v0 = acc[mf][nf][2*h], v1 = acc[mf][nf][2*h+1];
                    __nv_bfloat16 h0 = __float2bfloat16(v0);
                    __nv_bfloat16 h1 = __float2bfloat16(v1);
                    __nv_bfloat16 l0 = __float2bfloat16(v0 - __bfloat162float(h0));
                    __nv_bfloat16 l1 = __float2bfloat16(v1 - __bfloat162float(h1));
                    __nv_bfloat162 hh = __halves2bfloat162(h0, h1);
                    __nv_bfloat162 ll = __halves2bfloat162(l0, l1);
                    *(uint32_t*)&Ch[o] = *(uint32_t*)&hh;
                    *(uint32_t*)&Cl[o] = *(uint32_t*)&ll;
                }
            }
        }
    }
}

// ---------------------------------------------------------------------------
// fp32 -> split bf16 (hi/lo)
// ---------------------------------------------------------------------------
__global__ void __launch_bounds__(256)
split_f32(const float* __restrict__ in, __nv_bfloat16* __restrict__ hi,
          __nv_bfloat16* __restrict__ lo, long long n4)
{
    long long i = (long long)blockIdx.x * blockDim.x + threadIdx.x;
    if (i >= n4) return;
    float4 v = ((const float4*)in)[i];
    __nv_bfloat16 h0 = __float2bfloat16(v.x), h1 = __float2bfloat16(v.y);
    __nv_bfloat16 h2 = __float2bfloat16(v.z), h3 = __float2bfloat16(v.w);
    __nv_bfloat162 a = __halves2bfloat162(h0, h1), b = __halves2bfloat162(h2, h3);
    uint2 uh = { *(uint32_t*)&a, *(uint32_t*)&b };
    __nv_bfloat16 l0 = __float2bfloat16(v.x - __bfloat162float(h0));
    __nv_bfloat16 l1 = __float2bfloat16(v.y - __bfloat162float(h1));
    __nv_bfloat16 l2 = __float2bfloat16(v.z - __bfloat162float(h2));
    __nv_bfloat16 l3 = __float2bfloat16(v.w - __bfloat162float(h3));
    __nv_bfloat162 c = __halves2bfloat162(l0, l1), d = __halves2bfloat162(l2, l3);
    uint2 ulv = { *(uint32_t*)&c, *(uint32_t*)&d };
    ((uint2*)hi)[i] = uh;
    ((uint2*)lo)[i] = ulv;
}

// ---------------------------------------------------------------------------
// V [b][s][d] fp32 -> Vt hi/lo [b][d][s] split bf16 (32x32 smem transpose)
// ---------------------------------------------------------------------------
__global__ void __launch_bounds__(256)
transpose_split(const float* __restrict__ V, __nv_bfloat16* __restrict__ Th,
                __nv_bfloat16* __restrict__ Tl)
{
    __shared__ float t[32][33];
    const int b = blockIdx.z;
    const int s0 = blockIdx.x * 32, d0 = blockIdx.y * 32;
    const int tx = threadIdx.x & 31, ty = threadIdx.x >> 5;  // 32x8
    const float* Vb = V + (long long)b * SEQ * DIM;
    #pragma unroll
    for (int j = 0; j < 4; j++)
        t[ty + 8*j][tx] = Vb[(long long)(s0 + ty + 8*j) * DIM + d0 + tx];
    __syncthreads();
    __nv_bfloat16* Thb = Th + (long long)b * DIM * SEQ;
    __nv_bfloat16* Tlb = Tl + (long long)b * DIM * SEQ;
    #pragma unroll
    for (int j = 0; j < 4; j++) {
        float v = t[tx][ty + 8*j];
        __nv_bfloat16 h = __float2bfloat16(v);
        __nv_bfloat16 l = __float2bfloat16(v - __bfloat162float(h));
        long long o = (long long)(d0 + ty + 8*j) * SEQ + s0 + tx;
        Thb[o] = h;  Tlb[o] = l;
    }
}

// ---------------------------------------------------------------------------
// Row softmax (4096 cols), IN-PLACE: reads fp32 row, writes split-bf16 P
// into the same 16KB row (Ph first 8KB, Pl second 8KB). One block per row.
// ---------------------------------------------------------------------------
__device__ __forceinline__ float warpMax(float v) {
    #pragma unroll
    for (int o = 16; o; o >>= 1) v = fmaxf(v, __shfl_xor_sync(0xffffffffu, v, o));
    return v;
}
__device__ __forceinline__ float warpSum(float v) {
    #pragma unroll
    for (int o = 16; o; o >>= 1) v += __shfl_xor_sync(0xffffffffu, v, o);
    return v;
}

__global__ void __launch_bounds__(256)
softmax_inplace(float* __restrict__ SP)
{
    __shared__ float shm[8], shs[8];
    const size_t row = blockIdx.x;
    float* rowp = SP + row * (size_t)SEQ;
    const float4* r4 = (const float4*)rowp;
    const int tid = threadIdx.x, lane = tid & 31, wid = tid >> 5;

    float4 v[4];
    float m = -3.4e38f;
    #pragma unroll
    for (int i = 0; i < 4; i++) {
        v[i] = r4[tid + i * 256];
        m = fmaxf(m, fmaxf(fmaxf(v[i].x, v[i].y), fmaxf(v[i].z, v[i].w)));
    }
    m = warpMax(m);
    if (lane == 0) shm[wid] = m;
    __syncthreads();
    float bm = shm[0];
    #pragma unroll
    for (int i = 1; i < 8; i++) bm = fmaxf(bm, shm[i]);

    float s = 0.f;
    #pragma unroll
    for (int i = 0; i < 4; i++) {
        v[i].x = __expf(v[i].x - bm); v[i].y = __expf(v[i].y - bm);
        v[i].z = __expf(v[i].z - bm); v[i].w = __expf(v[i].w - bm);
        s += v[i].x + v[i].y + v[i].z + v[i].w;
    }
    s = warpSum(s);
    if (lane == 0) shs[wid] = s;
    __syncthreads();
    float bs = 0.f;
    #pragma unroll
    for (int i = 0; i < 8; i++) bs += shs[i];
    const float inv = 1.0f / bs;

    uint2* ph = (uint2*)rowp;
    uint2* pl = (uint2*)((__nv_bfloat16*)rowp + SEQ);
    #pragma unroll
    for (int i = 0; i < 4; i++) {
        float x0 = v[i].x * inv, x1 = v[i].y * inv, x2 = v[i].z * inv, x3 = v[i].w * inv;
        __nv_bfloat16 h0 = __float2bfloat16(x0), h1 = __float2bfloat16(x1);
        __nv_bfloat16 h2 = __float2bfloat16(x2), h3 = __float2bfloat16(x3);
        __nv_bfloat162 a = __halves2bfloat162(h0, h1), b = __halves2bfloat162(h2, h3);
        ph[tid + i * 256] = uint2{ *(uint32_t*)&a, *(uint32_t*)&b };
        __nv_bfloat16 l0 = __float2bfloat16(x0 - __bfloat162float(h0));
        __nv_bfloat16 l1 = __float2bfloat16(x1 - __bfloat162float(h1));
        __nv_bfloat16 l2 = __float2bfloat16(x2 - __bfloat162float(h2));
        __nv_bfloat16 l3 = __float2bfloat16(x3 - __bfloat162float(h3));
        __nv_bfloat162 c = __halves2bfloat162(l0, l1), d = __halves2bfloat162(l2, l3);
        pl[tid + i * 256] = uint2{ *(uint32_t*)&c, *(uint32_t*)&d };
    }
}

// ---------------------------------------------------------------------------
// Launch
// ---------------------------------------------------------------------------
extern "C" void kernel_launch(void* const* d_in, const int* in_sizes, int n_in,
                              void* d_out, int out_size)
{
    const float* x  = (const float*)d_in[0];
    const float* Wq = (const float*)d_in[1];
    const float* Wk = (const float*)d_in[2];
    const float* Wv = (const float*)d_in[3];
    float* out = (float*)d_out;

    __nv_bfloat16 *xh, *xl, *Wh, *Wl, *Qh, *Ql, *Kh, *Kl, *Vth, *Vtl;
    float *V, *SP;
    cudaGetSymbolAddress((void**)&xh, g_xh);   cudaGetSymbolAddress((void**)&xl, g_xl);
    cudaGetSymbolAddress((void**)&Wh, g_Wh);   cudaGetSymbolAddress((void**)&Wl, g_Wl);
    cudaGetSymbolAddress((void**)&Qh, g_Qh);   cudaGetSymbolAddress((void**)&Ql, g_Ql);
    cudaGetSymbolAddress((void**)&Kh, g_Kh);   cudaGetSymbolAddress((void**)&Kl, g_Kl);
    cudaGetSymbolAddress((void**)&V,  g_V);
    cudaGetSymbolAddress((void**)&Vth, g_Vth); cudaGetSymbolAddress((void**)&Vtl, g_Vtl);
    cudaGetSymbolAddress((void**)&SP, g_SP);

    cudaFuncSetAttribute(gemm_mma<0>, cudaFuncAttributeMaxDynamicSharedMemorySize, GEMM_SMEM);
    cudaFuncSetAttribute(gemm_mma<1>, cudaFuncAttributeMaxDynamicSharedMemorySize, GEMM_SMEM);

    const float scale = 1.0f / 32.0f;  // D^-0.5

    // 1) split inputs to hi/lo bf16
    split_f32<<<(MTOT * (long long)DIM / 4 + 255) / 256, 256>>>(x, xh, xl, (long long)MTOT * DIM / 4);
    const long long wn4 = (long long)DIM * DIM / 4;
    split_f32<<<(wn4 + 255) / 256, 256>>>(Wq, Wh + 0 * (size_t)DIM * DIM, Wl + 0 * (size_t)DIM * DIM, wn4);
    split_f32<<<(wn4 + 255) / 256, 256>>>(Wk, Wh + 1 * (size_t)DIM * DIM, Wl + 1 * (size_t)DIM * DIM, wn4);
    split_f32<<<(wn4 + 255) / 256, 256>>>(Wv, Wh + 2 * (size_t)DIM * DIM, Wl + 2 * (size_t)DIM * DIM, wn4);

    // 2) projections: [16384,1024] = x @ W^T
    {
        dim3 grid(DIM / 128, MTOT / 128, 1);
        gemm_mma<1><<<grid, 256, GEMM_SMEM>>>(xh, xl, Wh + 0 * (size_t)DIM * DIM, Wl + 0 * (size_t)DIM * DIM,
                                              nullptr, Qh, Ql, DIM, DIM, DIM, DIM, 1.f, 0, 0, 0);
        gemm_mma<1><<<grid, 256, GEMM_SMEM>>>(xh, xl, Wh + 1 * (size_t)DIM * DIM, Wl + 1 * (size_t)DIM * DIM,
                                              nullptr, Kh, Kl, DIM, DIM, DIM, DIM, 1.f, 0, 0, 0);
        gemm_mma<0><<<grid, 256, GEMM_SMEM>>>(xh, xl, Wh + 2 * (size_t)DIM * DIM, Wl + 2 * (size_t)DIM * DIM,
                                              V, nullptr, nullptr, DIM, DIM, DIM, DIM, 1.f, 0, 0, 0);
    }

    // 3) V -> Vt split (bf16 [b][d][s])
    transpose_split<<<dim3(SEQ / 32, DIM / 32, BATCH), 256>>>(V, Vth, Vtl);

    // 4) scores: SP[b] = scale * Q[b] @ K[b]^T   (fp32)
    gemm_mma<0><<<dim3(SEQ / 128, SEQ / 128, BATCH), 256, GEMM_SMEM>>>(
        Qh, Ql, Kh, Kl, SP, nullptr, nullptr,
        DIM, DIM, DIM, SEQ, scale,
        (long long)SEQ * DIM, (long long)SEQ * DIM, (long long)SEQ * SEQ);

    // 5) softmax in-place -> split bf16 P (row stride 2*SEQ bf16)
    softmax_inplace<<<BATCH * SEQ, 256>>>(SP);

    // 6) out[b] = P[b] @ Vt[b]^T   (Ph rows at stride 2*SEQ, Pl = Ph + SEQ)
    {
        const __nv_bfloat16* Phb = (const __nv_bfloat16*)SP;
        const __nv_bfloat16* Plb = Phb + SEQ;
        gemm_mma<0><<<dim3(DIM / 128, SEQ / 128, BATCH), 256, GEMM_SMEM>>>(
            Phb, Plb, Vth, Vtl, out, nullptr, nullptr,
            SEQ, 2 * SEQ, SEQ, DIM, 1.f,
            (long long)SEQ * 2 * SEQ, (long long)DIM * SEQ, (long long)SEQ * DIM);
    }
}

// round 14
// speedup vs baseline: 1.3609x; 1.2966x over previous
#include <cuda_runtime.h>
#include <cuda_bf16.h>
#include <cuda_fp16.h>
#include <math.h>
#include <stdint.h>

// Problem: B=4, S=4096, D=1024  (single-head attention, fp32 I/O)
#define BATCH 4
#define SEQ   4096
#define DIM   1024
#define MTOT  (BATCH*SEQ)   // 16384

// ---------------------------------------------------------------------------
// Static device scratch
// ---------------------------------------------------------------------------
__device__ __align__(256) __nv_bfloat16 g_xh[(size_t)MTOT * DIM];
__device__ __align__(256) __nv_bfloat16 g_xl[(size_t)MTOT * DIM];
__device__ __align__(256) __nv_bfloat16 g_Wh[3][(size_t)DIM * DIM];
__device__ __align__(256) __nv_bfloat16 g_Wl[3][(size_t)DIM * DIM];
__device__ __align__(256) __nv_bfloat16 g_Qh[(size_t)MTOT * DIM];
__device__ __align__(256) __nv_bfloat16 g_Ql[(size_t)MTOT * DIM];
__device__ __align__(256) __nv_bfloat16 g_Kh[(size_t)MTOT * DIM];
__device__ __align__(256) __nv_bfloat16 g_Kl[(size_t)MTOT * DIM];
__device__ __align__(256) float         g_V [(size_t)MTOT * DIM];
__device__ __align__(256) __half        g_Vt[(size_t)BATCH * DIM * SEQ];   // fp16 V^T
// Union buffer: fp32 scores, then overwritten in-place by fp16 P.
// Row r: fp32 Sc row = 16KB; after softmax first 8KB hold P (fp16[4096]).
__device__ __align__(256) float         g_SP[(size_t)BATCH * SEQ * SEQ];

// ---------------------------------------------------------------------------
// PTX helpers — baseline (non arch-variant) instructions only
// ---------------------------------------------------------------------------
__device__ __forceinline__ uint32_t smem_u32(const void* p) {
    uint32_t a;
    asm("{ .reg .u64 t; cvta.to.shared.u64 t, %1; cvt.u32.u64 %0, t; }"
        : "=r"(a) : "l"(p));
    return a;
}
__device__ __forceinline__ uint32_t swz128(uint32_t o) { return o ^ ((o >> 3) & 0x70); }

__device__ __forceinline__ void cp16(uint32_t dst, const void* src) {
    asm volatile("cp.async.cg.shared.global [%0], [%1], 16;"
                 :: "r"(dst), "l"(__cvta_generic_to_global(src)) : "memory");
}
#define CP_COMMIT() asm volatile("cp.async.commit_group;" ::: "memory")
#define CP_WAIT1()  asm volatile("cp.async.wait_group 1;" ::: "memory")

__device__ __forceinline__ void ldsm_x4(uint32_t& r0, uint32_t& r1, uint32_t& r2,
                                        uint32_t& r3, uint32_t addr) {
    asm volatile("ldmatrix.sync.aligned.m8n8.x4.shared.b16 {%0,%1,%2,%3}, [%4];"
                 : "=r"(r0), "=r"(r1), "=r"(r2), "=r"(r3) : "r"(addr));
}
__device__ __forceinline__ void mma_bf16(float* d, const uint32_t* a, const uint32_t* b) {
    asm volatile(
        "mma.sync.aligned.m16n8k16.row.col.f32.bf16.bf16.f32 "
        "{%0,%1,%2,%3}, {%4,%5,%6,%7}, {%8,%9}, {%0,%1,%2,%3};"
        : "+f"(d[0]), "+f"(d[1]), "+f"(d[2]), "+f"(d[3])
        : "r"(a[0]), "r"(a[1]), "r"(a[2]), "r"(a[3]), "r"(b[0]), "r"(b[1]));
}
__device__ __forceinline__ void mma_f16(float* d, const uint32_t* a, const uint32_t* b) {
    asm volatile(
        "mma.sync.aligned.m16n8k16.row.col.f32.f16.f16.f32 "
        "{%0,%1,%2,%3}, {%4,%5,%6,%7}, {%8,%9}, {%0,%1,%2,%3};"
        : "+f"(d[0]), "+f"(d[1]), "+f"(d[2]), "+f"(d[3])
        : "r"(a[0]), "r"(a[1]), "r"(a[2]), "r"(a[3]), "r"(b[0]), "r"(b[1]));
}

// ---------------------------------------------------------------------------
// Split-bf16 tensor-core GEMM (EXACT R8 baseline, 3151us config):
//   C[M,N] = alpha * (A_hi+A_lo) @ (B_hi+B_lo)^T ; 3 MMAs per k-step.
//   CTA tile 128x128, K chunk 64 (128B SW128 rows), 2-stage cp.async pipe.
//   8 warps, 2(m) x 4(n); warp tile 64x32.
//   EPI 0: fp32 out (alpha);  EPI 1: split hi/lo bf16 out.
// ---------------------------------------------------------------------------
#define KCHUNK       64
#define TILE_BYTES   16384              // 128 rows * 128B
#define STAGE_BYTES  (4 * TILE_BYTES)   // Ahi, Alo, Bhi, Blo
#define NSTAGES      2
#define GEMM_SMEM    (NSTAGES * STAGE_BYTES)   // 131072 B

template <int EPI>
__global__ void __launch_bounds__(256, 1)
gemm_mma(const __nv_bfloat16* __restrict__ Ah, const __nv_bfloat16* __restrict__ Al,
         const __nv_bfloat16* __restrict__ Bh, const __nv_bfloat16* __restrict__ Bl,
         float* __restrict__ Cf, __nv_bfloat16* __restrict__ Ch, __nv_bfloat16* __restrict__ Cl,
         int K, int lda, int ldb, int ldc, float alpha,
         long long sA, long long sB, long long sC)
{
    extern __shared__ __align__(1024) char smem[];
    const uint32_t sbase = smem_u32(smem);
    const int tid  = threadIdx.x;
    const int wid  = tid >> 5, lane = tid & 31;
    const int wm   = wid & 1;
    const int wn   = wid >> 1;

    Ah += blockIdx.z * sA;  Al += blockIdx.z * sA;
    Bh += blockIdx.z * sB;  Bl += blockIdx.z * sB;
    const int m0 = blockIdx.y * 128;
    const int n0 = blockIdx.x * 128;

    auto load_chunk = [&](int c) {
        const uint32_t stage = sbase + (c & (NSTAGES - 1)) * STAGE_BYTES;
        const int kb = c * KCHUNK;
        #pragma unroll
        for (int i = 0; i < 16; i++) {
            const int idx = tid + i * 256;
            const int t   = i >> 2;           // 0:Ahi 1:Alo 2:Bhi 3:Blo
            const int w   = idx & 1023;
            const int r   = w >> 3;
            const int seg = w & 7;
            const __nv_bfloat16* gp;
            if (t == 0)      gp = Ah + (long long)(m0 + r) * lda + kb + seg * 8;
            else if (t == 1) gp = Al + (long long)(m0 + r) * lda + kb + seg * 8;
            else if (t == 2) gp = Bh + (long long)(n0 + r) * ldb + kb + seg * 8;
            else             gp = Bl + (long long)(n0 + r) * ldb + kb + seg * 8;
            cp16(stage + t * TILE_BYTES + swz128(r * 128 + seg * 16), gp);
        }
        CP_COMMIT();
    };

    load_chunk(0);
    load_chunk(1);

    float acc[4][4][4];
    #pragma unroll
    for (int i = 0; i < 4; i++)
        #pragma unroll
        for (int j = 0; j < 4; j++)
            #pragma unroll
            for (int q = 0; q < 4; q++) acc[i][j][q] = 0.f;

    const int lrow = lane & 15;
    const int lkof = (lane >> 4) * 16;
    const int arow = wm * 64 + lrow;
    const int brow = wn * 32 + lrow;

    const int C = K / KCHUNK;
    for (int c = 0; c < C; c++) {
        CP_WAIT1();
        __syncthreads();
        const uint32_t st = sbase + (c & (NSTAGES - 1)) * STAGE_BYTES;

        #pragma unroll
        for (int k16 = 0; k16 < 4; k16++) {
            const uint32_t kb = k16 * 32 + lkof;
            uint32_t ah[4][4], al[4][4], bh[4][2], bl[4][2];
            #pragma unroll
            for (int mf = 0; mf < 4; mf++) {
                const uint32_t ro = swz128((arow + mf * 16) * 128 + kb);
                ldsm_x4(ah[mf][0], ah[mf][1], ah[mf][2], ah[mf][3], st + ro);
                ldsm_x4(al[mf][0], al[mf][1], al[mf][2], al[mf][3], st + TILE_BYTES + ro);
            }
            #pragma unroll
            for (int p = 0; p < 2; p++) {
                const uint32_t ro = swz128((brow + p * 16) * 128 + kb);
                uint32_t r0, r1, r2, r3;
                ldsm_x4(r0, r1, r2, r3, st + 2 * TILE_BYTES + ro);
                bh[2*p][0] = r0; bh[2*p][1] = r2; bh[2*p+1][0] = r1; bh[2*p+1][1] = r3;
                ldsm_x4(r0, r1, r2, r3, st + 3 * TILE_BYTES + ro);
                bl[2*p][0] = r0; bl[2*p][1] = r2; bl[2*p+1][0] = r1; bl[2*p+1][1] = r3;
            }
            #pragma unroll
            for (int mf = 0; mf < 4; mf++)
                #pragma unroll
                for (int nf = 0; nf < 4; nf++) {
                    mma_bf16(acc[mf][nf], ah[mf], bh[nf]);
                    mma_bf16(acc[mf][nf], ah[mf], bl[nf]);
                    mma_bf16(acc[mf][nf], al[mf], bh[nf]);
                }
        }
        __syncthreads();
        if (c + NSTAGES < C) load_chunk(c + NSTAGES);
        else CP_COMMIT();
    }

    const int tq = lane >> 2;
    const int tr = (lane & 3) * 2;
    if (EPI == 0) {
        float* Cb = Cf + blockIdx.z * sC;
        #pragma unroll
        for (int mf = 0; mf < 4; mf++) {
            const int r = m0 + wm * 64 + mf * 16 + tq;
            #pragma unroll
            for (int nf = 0; nf < 4; nf++) {
                const int col = n0 + wn * 32 + nf * 8 + tr;
                float2 v0 = { acc[mf][nf][0] * alpha, acc[mf][nf][1] * alpha };
                float2 v1 = { acc[mf][nf][2] * alpha, acc[mf][nf][3] * alpha };
                *(float2*)&Cb[(long long)r * ldc + col]       = v0;
                *(float2*)&Cb[(long long)(r + 8) * ldc + col] = v1;
            }
        }
    } else {
        #pragma unroll
        for (int mf = 0; mf < 4; mf++) {
            const int r = m0 + wm * 64 + mf * 16 + tq;
            #pragma unroll
            for (int nf = 0; nf < 4; nf++) {
                const int col = n0 + wn * 32 + nf * 8 + tr;
                #pragma unroll
                for (int h = 0; h < 2; h++) {
                    const long long o = (long long)(r + 8 * h) * ldc + col;
                    float v0 = acc[mf][nf][2*h], v1 = acc[mf][nf][2*h+1];
                    __nv_bfloat16 h0 = __float2bfloat16(v0);
                    __nv_bfloat16 h1 = __float2bfloat16(v1);
                    __nv_bfloat16 l0 = __float2bfloat16(v0 - __bfloat162float(h0));
                    __nv_bfloat16 l1 = __float2bfloat16(v1 - __bfloat162float(h1));
                    __nv_bfloat162 hh = __halves2bfloat162(h0, h1);
                    __nv_bfloat162 ll = __halves2bfloat162(l0, l1);
                    *(uint32_t*)&Ch[o] = *(uint32_t*)&hh;
                    *(uint32_t*)&Cl[o] = *(uint32_t*)&ll;
                }
            }
        }
    }
}

// ---------------------------------------------------------------------------
// Single-MMA fp16 GEMM:  C[M,N] = A @ B^T   (A [M,K] fp16, B [N,K] fp16)
//   Same R8 schedule: CTA 128x128, KCHUNK 64 (128B SW128 rows), 2 stages,
//   2 tiles/stage (32KB) -> 64KB smem. 1 MMA per k-step. fp32 out.
// ---------------------------------------------------------------------------
#define F16_STAGE   (2 * TILE_BYTES)    // A, B = 32KB
#define F16_SMEM    (NSTAGES * F16_STAGE)   // 65536 B

__global__ void __launch_bounds__(256, 1)
gemm_f16(const __half* __restrict__ A, const __half* __restrict__ B,
         float* __restrict__ Cf,
         int K, int lda, int ldb, int ldc,
         long long sA, long long sB, long long sC)
{
    extern __shared__ __align__(1024) char smem[];
    const uint32_t sbase = smem_u32(smem);
    const int tid  = threadIdx.x;
    const int wid  = tid >> 5, lane = tid & 31;
    const int wm   = wid & 1;
    const int wn   = wid >> 1;

    A += blockIdx.z * sA;
    B += blockIdx.z * sB;
    const int m0 = blockIdx.y * 128;
    const int n0 = blockIdx.x * 128;

    // 2048 x 16B cp.async per chunk (8 per thread)
    auto load_chunk = [&](int c) {
        const uint32_t stage = sbase + (c & (NSTAGES - 1)) * F16_STAGE;
        const int kb = c * KCHUNK;
        #pragma unroll
        for (int i = 0; i < 8; i++) {
            const int idx = tid + i * 256;
            const int t   = idx >> 10;        // 0:A 1:B
            const int w   = idx & 1023;
            const int r   = w >> 3;
            const int seg = w & 7;
            const __half* gp = t ? B + (long long)(n0 + r) * ldb + kb + seg * 8
                                 : A + (long long)(m0 + r) * lda + kb + seg * 8;
            cp16(stage + t * TILE_BYTES + swz128(r * 128 + seg * 16), gp);
        }
        CP_COMMIT();
    };

    load_chunk(0);
    load_chunk(1);

    float acc[4][4][4];
    #pragma unroll
    for (int i = 0; i < 4; i++)
        #pragma unroll
        for (int j = 0; j < 4; j++)
            #pragma unroll
            for (int q = 0; q < 4; q++) acc[i][j][q] = 0.f;

    const int lrow = lane & 15;
    const int lkof = (lane >> 4) * 16;
    const int arow = wm * 64 + lrow;
    const int brow = wn * 32 + lrow;

    const int C = K / KCHUNK;
    for (int c = 0; c < C; c++) {
        CP_WAIT1();
        __syncthreads();
        const uint32_t st = sbase + (c & (NSTAGES - 1)) * F16_STAGE;

        #pragma unroll
        for (int k16 = 0; k16 < 4; k16++) {
            const uint32_t kb = k16 * 32 + lkof;
            uint32_t a[4][4], b[4][2];
            #pragma unroll
            for (int mf = 0; mf < 4; mf++) {
                const uint32_t ro = swz128((arow + mf * 16) * 128 + kb);
                ldsm_x4(a[mf][0], a[mf][1], a[mf][2], a[mf][3], st + ro);
            }
            #pragma unroll
            for (int p = 0; p < 2; p++) {
                const uint32_t ro = swz128((brow + p * 16) * 128 + kb);
                uint32_t r0, r1, r2, r3;
                ldsm_x4(r0, r1, r2, r3, st + TILE_BYTES + ro);
                b[2*p][0] = r0; b[2*p][1] = r2; b[2*p+1][0] = r1; b[2*p+1][1] = r3;
            }
            #pragma unroll
            for (int mf = 0; mf < 4; mf++)
                #pragma unroll
                for (int nf = 0; nf < 4; nf++)
                    mma_f16(acc[mf][nf], a[mf], b[nf]);
        }
        __syncthreads();
        if (c + NSTAGES < C) load_chunk(c + NSTAGES);
        else CP_COMMIT();
    }

    const int tq = lane >> 2;
    const int tr = (lane & 3) * 2;
    float* Cb = Cf + blockIdx.z * sC;
    #pragma unroll
    for (int mf = 0; mf < 4; mf++) {
        const int r = m0 + wm * 64 + mf * 16 + tq;
        #pragma unroll
        for (int nf = 0; nf < 4; nf++) {
            const int col = n0 + wn * 32 + nf * 8 + tr;
            float2 v0 = { acc[mf][nf][0], acc[mf][nf][1] };
            float2 v1 = { acc[mf][nf][2], acc[mf][nf][3] };
            *(float2*)&Cb[(long long)r * ldc + col]       = v0;
            *(float2*)&Cb[(long long)(r + 8) * ldc + col] = v1;
        }
    }
}

// ---------------------------------------------------------------------------
// fp32 -> split bf16 (hi/lo)
// ---------------------------------------------------------------------------
__global__ void __launch_bounds__(256)
split_f32(const float* __restrict__ in, __nv_bfloat16* __restrict__ hi,
          __nv_bfloat16* __restrict__ lo, long long n4)
{
    long long i = (long long)blockIdx.x * blockDim.x + threadIdx.x;
    if (i >= n4) return;
    float4 v = ((const float4*)in)[i];
    __nv_bfloat16 h0 = __float2bfloat16(v.x), h1 = __float2bfloat16(v.y);
    __nv_bfloat16 h2 = __float2bfloat16(v.z), h3 = __float2bfloat16(v.w);
    __nv_bfloat162 a = __halves2bfloat162(h0, h1), b = __halves2bfloat162(h2, h3);
    uint2 uh = { *(uint32_t*)&a, *(uint32_t*)&b };
    __nv_bfloat16 l0 = __float2bfloat16(v.x - __bfloat162float(h0));
    __nv_bfloat16 l1 = __float2bfloat16(v.y - __bfloat162float(h1));
    __nv_bfloat16 l2 = __float2bfloat16(v.z - __bfloat162float(h2));
    __nv_bfloat16 l3 = __float2bfloat16(v.w - __bfloat162float(h3));
    __nv_bfloat162 c = __halves2bfloat162(l0, l1), d = __halves2bfloat162(l2, l3);
    uint2 ulv = { *(uint32_t*)&c, *(uint32_t*)&d };
    ((uint2*)hi)[i] = uh;
    ((uint2*)lo)[i] = ulv;
}

// ---------------------------------------------------------------------------
// V [b][s][d] fp32 -> Vt fp16 [b][d][s]  (32x32 smem transpose)
// ---------------------------------------------------------------------------
__global__ void __launch_bounds__(256)
transpose_f16(const float* __restrict__ V, __half* __restrict__ T)
{
    __shared__ float t[32][33];
    const int b = blockIdx.z;
    const int s0 = blockIdx.x * 32, d0 = blockIdx.y * 32;
    const int tx = threadIdx.x & 31, ty = threadIdx.x >> 5;  // 32x8
    const float* Vb = V + (long long)b * SEQ * DIM;
    #pragma unroll
    for (int j = 0; j < 4; j++)
        t[ty + 8*j][tx] = Vb[(long long)(s0 + ty + 8*j) * DIM + d0 + tx];
    __syncthreads();
    __half* Tb = T + (long long)b * DIM * SEQ;
    #pragma unroll
    for (int j = 0; j < 4; j++) {
        long long o = (long long)(d0 + ty + 8*j) * SEQ + s0 + tx;
        Tb[o] = __float2half(t[tx][ty + 8*j]);
    }
}

// ---------------------------------------------------------------------------
// Row softmax (4096 cols), IN-PLACE: reads fp32 row, writes fp16 P into the
// first 8KB of the same 16KB row. One block per row.
// ---------------------------------------------------------------------------
__device__ __forceinline__ float warpMax(float v) {
    #pragma unroll
    for (int o = 16; o; o >>= 1) v = fmaxf(v, __shfl_xor_sync(0xffffffffu, v, o));
    return v;
}
__device__ __forceinline__ float warpSum(float v) {
    #pragma unroll
    for (int o = 16; o; o >>= 1) v += __shfl_xor_sync(0xffffffffu, v, o);
    return v;
}

__global__ void __launch_bounds__(256)
softmax_inplace(float* __restrict__ SP)
{
    __shared__ float shm[8], shs[8];
    const size_t row = blockIdx.x;
    float* rowp = SP + row * (size_t)SEQ;
    const float4* r4 = (const float4*)rowp;
    const int tid = threadIdx.x, lane = tid & 31, wid = tid >> 5;

    float4 v[4];
    float m = -3.4e38f;
    #pragma unroll
    for (int i = 0; i < 4; i++) {
        v[i] = r4[tid + i * 256];
        m = fmaxf(m, fmaxf(fmaxf(v[i].x, v[i].y), fmaxf(v[i].z, v[i].w)));
    }
    m = warpMax(m);
    if (lane == 0) shm[wid] = m;
    __syncthreads();
    float bm = shm[0];
    #pragma unroll
    for (int i = 1; i < 8; i++) bm = fmaxf(bm, shm[i]);

    float s = 0.f;
    #pragma unroll
    for (int i = 0; i < 4; i++) {
        v[i].x = __expf(v[i].x - bm); v[i].y = __expf(v[i].y - bm);
        v[i].z = __expf(v[i].z - bm); v[i].w = __expf(v[i].w - bm);
        s += v[i].x + v[i].y + v[i].z + v[i].w;
    }
    s = warpSum(s);
    if (lane == 0) shs[wid] = s;
    __syncthreads();
    float bs = 0.f;
    #pragma unroll
    for (int i = 0; i < 8; i++) bs += shs[i];
    const float inv = 1.0f / bs;

    // fp16 P: 4096 halfs = 1024 uint2; each thread writes 4
    uint2* ph = (uint2*)rowp;
    #pragma unroll
    for (int i = 0; i < 4; i++) {
        float x0 = v[i].x * inv, x1 = v[i].y * inv, x2 = v[i].z * inv, x3 = v[i].w * inv;
        __half2 a = __halves2half2(__float2half(x0), __float2half(x1));
        __half2 b = __halves2half2(__float2half(x2), __float2half(x3));
        ph[tid + i * 256] = uint2{ *(uint32_t*)&a, *(uint32_t*)&b };
    }
}

// ---------------------------------------------------------------------------
// Launch
// ---------------------------------------------------------------------------
extern "C" void kernel_launch(void* const* d_in, const int* in_sizes, int n_in,
                              void* d_out, int out_size)
{
    const float* x  = (const float*)d_in[0];
    const float* Wq = (const float*)d_in[1];
    const float* Wk = (const float*)d_in[2];
    const float* Wv = (const float*)d_in[3];
    float* out = (float*)d_out;

    __nv_bfloat16 *xh, *xl, *Wh, *Wl, *Qh, *Ql, *Kh, *Kl;
    __half *Vt;
    float *V, *SP;
    cudaGetSymbolAddress((void**)&xh, g_xh);   cudaGetSymbolAddress((void**)&xl, g_xl);
    cudaGetSymbolAddress((void**)&Wh, g_Wh);   cudaGetSymbolAddress((void**)&Wl, g_Wl);
    cudaGetSymbolAddress((void**)&Qh, g_Qh);   cudaGetSymbolAddress((void**)&Ql, g_Ql);
    cudaGetSymbolAddress((void**)&Kh, g_Kh);   cudaGetSymbolAddress((void**)&Kl, g_Kl);
    cudaGetSymbolAddress((void**)&V,  g_V);
    cudaGetSymbolAddress((void**)&Vt, g_Vt);
    cudaGetSymbolAddress((void**)&SP, g_SP);

    cudaFuncSetAttribute(gemm_mma<0>, cudaFuncAttributeMaxDynamicSharedMemorySize, GEMM_SMEM);
    cudaFuncSetAttribute(gemm_mma<1>, cudaFuncAttributeMaxDynamicSharedMemorySize, GEMM_SMEM);
    cudaFuncSetAttribute(gemm_f16,    cudaFuncAttributeMaxDynamicSharedMemorySize, F16_SMEM);

    const float scale = 1.0f / 32.0f;  // D^-0.5

    // 1) split inputs to hi/lo bf16
    split_f32<<<(MTOT * (long long)DIM / 4 + 255) / 256, 256>>>(x, xh, xl, (long long)MTOT * DIM / 4);
    const long long wn4 = (long long)DIM * DIM / 4;
    split_f32<<<(wn4 + 255) / 256, 256>>>(Wq, Wh + 0 * (size_t)DIM * DIM, Wl + 0 * (size_t)DIM * DIM, wn4);
    split_f32<<<(wn4 + 255) / 256, 256>>>(Wk, Wh + 1 * (size_t)DIM * DIM, Wl + 1 * (size_t)DIM * DIM, wn4);
    split_f32<<<(wn4 + 255) / 256, 256>>>(Wv, Wh + 2 * (size_t)DIM * DIM, Wl + 2 * (size_t)DIM * DIM, wn4);

    // 2) projections: [16384,1024] = x @ W^T   (split-bf16, 3-MMA)
    {
        dim3 grid(DIM / 128, MTOT / 128, 1);
        gemm_mma<1><<<grid, 256, GEMM_SMEM>>>(xh, xl, Wh + 0 * (size_t)DIM * DIM, Wl + 0 * (size_t)DIM * DIM,
                                              nullptr, Qh, Ql, DIM, DIM, DIM, DIM, 1.f, 0, 0, 0);
        gemm_mma<1><<<grid, 256, GEMM_SMEM>>>(xh, xl, Wh + 1 * (size_t)DIM * DIM, Wl + 1 * (size_t)DIM * DIM,
                                              nullptr, Kh, Kl, DIM, DIM, DIM, DIM, 1.f, 0, 0, 0);
        gemm_mma<0><<<grid, 256, GEMM_SMEM>>>(xh, xl, Wh + 2 * (size_t)DIM * DIM, Wl + 2 * (size_t)DIM * DIM,
                                              V, nullptr, nullptr, DIM, DIM, DIM, DIM, 1.f, 0, 0, 0);
    }

    // 3) V -> Vt fp16 [b][d][s]
    transpose_f16<<<dim3(SEQ / 32, DIM / 32, BATCH), 256>>>(V, Vt);

    // 4) scores: SP[b] = scale * Q[b] @ K[b]^T   (split-bf16, 3-MMA, fp32 out)
    gemm_mma<0><<<dim3(SEQ / 128, SEQ / 128, BATCH), 256, GEMM_SMEM>>>(
        Qh, Ql, Kh, Kl, SP, nullptr, nullptr,
        DIM, DIM, DIM, SEQ, scale,
        (long long)SEQ * DIM, (long long)SEQ * DIM, (long long)SEQ * SEQ);

    // 5) softmax in-place -> fp16 P (row stride 2*SEQ halfs = 16KB)
    softmax_inplace<<<BATCH * SEQ, 256>>>(SP);

    // 6) out[b] = P[b] @ Vt[b]^T   (single-MMA fp16)
    {
        const __half* Pb = (const __half*)SP;
        gemm_f16<<<dim3(DIM / 128, SEQ / 128, BATCH), 256, F16_SMEM>>>(
            Pb, Vt, out,
            SEQ, 2 * SEQ, SEQ, DIM,
            (long long)SEQ * 2 * SEQ, (long long)DIM * SEQ, (long long)SEQ * DIM);
    }
}